// round 1
// baseline (speedup 1.0000x reference)
#include <cuda_runtime.h>
#include <math.h>

#define B_  64
#define T_  512
#define D_  512
#define H_  512
#define MTOT (B_ * T_)   // 32768 GEMM rows

// Scratch for the three input projections: xz, xr, xh  (each [B*T, H] fp32)
__device__ float g_proj[3][(size_t)MTOT * H_];

// ---------------------------------------------------------------------------
// Kernel 1: C[z] = X @ W[z], z in {0,1,2} selecting kz/kr/kh.
// Classic 128x128x8 tiled SGEMM, 256 threads, 8x8 accumulators per thread.
// M=32768, N=512, K=512 — all dims divide tile sizes, no bounds checks.
// ---------------------------------------------------------------------------
__global__ __launch_bounds__(256)
void gemm3_kernel(const float* __restrict__ X,
                  const float* __restrict__ Kz,
                  const float* __restrict__ Kr,
                  const float* __restrict__ Kh)
{
    constexpr int BM = 128, BN = 128, BK = 8;

    __shared__ float As[BK][BM];   // A tile stored K-major (transposed on load)
    __shared__ float Bs[BK][BN];

    const float* W = (blockIdx.z == 0) ? Kz : (blockIdx.z == 1) ? Kr : Kh;
    float* C = g_proj[blockIdx.z];

    const int mBase = blockIdx.y * BM;
    const int nBase = blockIdx.x * BN;
    const int tid   = threadIdx.x;

    // A tile loaders: 128 rows x 8 cols, one float4 per thread
    const int aRow = tid >> 1;           // 0..127
    const int aCol = (tid & 1) * 4;      // 0 or 4
    // B tile loaders: 8 rows x 128 cols, one float4 per thread
    const int bRow = tid >> 5;           // 0..7
    const int bCol = (tid & 31) * 4;     // 0..124

    const int tr = tid >> 4;             // 0..15 -> row group
    const int tc = tid & 15;             // 0..15 -> col group

    float acc[8][8];
    #pragma unroll
    for (int i = 0; i < 8; ++i)
        #pragma unroll
        for (int j = 0; j < 8; ++j) acc[i][j] = 0.0f;

    const float* Aptr = X + (size_t)mBase * D_;
    const float* Bptr = W + nBase;

    for (int k0 = 0; k0 < D_; k0 += BK) {
        float4 a4 = *reinterpret_cast<const float4*>(Aptr + (size_t)aRow * D_ + k0 + aCol);
        As[aCol + 0][aRow] = a4.x;
        As[aCol + 1][aRow] = a4.y;
        As[aCol + 2][aRow] = a4.z;
        As[aCol + 3][aRow] = a4.w;

        float4 b4 = *reinterpret_cast<const float4*>(Bptr + (size_t)(k0 + bRow) * H_ + bCol);
        *reinterpret_cast<float4*>(&Bs[bRow][bCol]) = b4;

        __syncthreads();

        #pragma unroll
        for (int k = 0; k < BK; ++k) {
            float ra[8], rb[8];
            #pragma unroll
            for (int i = 0; i < 8; i += 4) {
                float4 v = *reinterpret_cast<const float4*>(&As[k][tr * 8 + i]);
                ra[i] = v.x; ra[i+1] = v.y; ra[i+2] = v.z; ra[i+3] = v.w;
            }
            #pragma unroll
            for (int j = 0; j < 8; j += 4) {
                float4 v = *reinterpret_cast<const float4*>(&Bs[k][tc * 8 + j]);
                rb[j] = v.x; rb[j+1] = v.y; rb[j+2] = v.z; rb[j+3] = v.w;
            }
            #pragma unroll
            for (int i = 0; i < 8; ++i)
                #pragma unroll
                for (int j = 0; j < 8; ++j)
                    acc[i][j] = fmaf(ra[i], rb[j], acc[i][j]);
        }
        __syncthreads();
    }

    #pragma unroll
    for (int i = 0; i < 8; ++i) {
        size_t row = (size_t)(mBase + tr * 8 + i);
        float4* outp = reinterpret_cast<float4*>(C + row * H_ + nBase + tc * 8);
        outp[0] = make_float4(acc[i][0], acc[i][1], acc[i][2], acc[i][3]);
        outp[1] = make_float4(acc[i][4], acc[i][5], acc[i][6], acc[i][7]);
    }
}

// ---------------------------------------------------------------------------
// Kernel 2: diagonal recurrence scan. One thread per (b, h) lane; T=512
// sequential steps. Consecutive threads -> consecutive h -> coalesced.
//   r = tanh(xr + h*mr) + 1
//   z = sigmoid(xz + h*mz)
//   h = z*h + (1-z)*tanh(xh + r*h)
// ---------------------------------------------------------------------------
__global__ __launch_bounds__(128)
void scan_kernel(const float* __restrict__ h0,
                 const float* __restrict__ mz, const float* __restrict__ mr,
                 const float* __restrict__ bz, const float* __restrict__ br,
                 float* __restrict__ out)
{
    const int gid = blockIdx.x * blockDim.x + threadIdx.x;   // 0 .. B*H-1
    const int b = gid / H_;
    const int h = gid % H_;

    float hv  = h0[gid];
    const float mzv = mz[h];
    const float mrv = mr[h];
    const float bzv = bz[h];
    const float brv = br[h];

    const size_t base = (size_t)b * T_ * H_ + h;
    const float* xz = g_proj[0] + base;
    const float* xr = g_proj[1] + base;
    const float* xh = g_proj[2] + base;
    float* o = out + base;

    for (int t = 0; t < T_; ++t) {
        const size_t off = (size_t)t * H_;
        float vz = xz[off] + bzv;
        float vr = xr[off] + brv;
        float vh = xh[off];

        float r  = tanhf(fmaf(hv, mrv, vr)) + 1.0f;
        float ze = __expf(-fmaf(hv, mzv, vz));
        float z  = 1.0f / (1.0f + ze);
        float ht = tanhf(fmaf(r, hv, vh));
        hv = fmaf(z, hv, (1.0f - z) * ht);
        o[off] = hv;
    }
}

// ---------------------------------------------------------------------------
extern "C" void kernel_launch(void* const* d_in, const int* in_sizes, int n_in,
                              void* d_out, int out_size)
{
    const float* x  = (const float*)d_in[0];
    const float* h0 = (const float*)d_in[1];
    const float* kz = (const float*)d_in[2];
    const float* kr = (const float*)d_in[3];
    const float* kh = (const float*)d_in[4];
    const float* mz = (const float*)d_in[5];
    const float* mr = (const float*)d_in[6];
    const float* bz = (const float*)d_in[7];
    const float* br = (const float*)d_in[8];
    float* out = (float*)d_out;

    dim3 grid(H_ / 128, MTOT / 128, 3);   // (4, 256, 3) = 3072 CTAs
    gemm3_kernel<<<grid, 256>>>(x, kz, kr, kh);

    scan_kernel<<<(B_ * H_) / 128, 128>>>(h0, mz, mr, bz, br, out);
}

// round 3
// speedup vs baseline: 2.3371x; 2.3371x over previous
#include <cuda_runtime.h>
#include <cuda_bf16.h>
#include <cstdint>
#include <math.h>

#define B_   64
#define T_   512
#define D_   512
#define H_   512
#define MTOT (B_ * T_)          // 32768 GEMM rows

// ---------------------------------------------------------------------------
// Scratch (static __device__ — allocation-guard safe)
// ---------------------------------------------------------------------------
// projections xz, xr, xh (fp32) + 8-step pad so the scan prefetch ring can
// read past the end harmlessly.
__device__ float g_proj[3][(size_t)MTOT * H_ + 8 * H_];
// bf16 hi/lo split of x
__device__ __nv_bfloat16 g_Ahi[(size_t)MTOT * D_];
__device__ __nv_bfloat16 g_Alo[(size_t)MTOT * D_];
// bf16 hi/lo split of W^T (stored [N][K] K-major)
__device__ __nv_bfloat16 g_WThi[3][H_ * D_];
__device__ __nv_bfloat16 g_WTlo[3][H_ * D_];

// ---------------------------------------------------------------------------
// helpers
// ---------------------------------------------------------------------------
__device__ __forceinline__ uint32_t smem_u32(const void* p) {
    return (uint32_t)__cvta_generic_to_shared(p);
}

__device__ __forceinline__ void cp16(uint32_t dst, const void* src) {
    asm volatile("cp.async.cg.shared.global [%0], [%1], 16;"
                 :: "r"(dst), "l"(src) : "memory");
}
#define CP_COMMIT() asm volatile("cp.async.commit_group;" ::: "memory")
#define CP_WAIT(n)  asm volatile("cp.async.wait_group %0;" :: "n"(n) : "memory")

__device__ __forceinline__ void ldmatrix_x4(uint32_t& r0, uint32_t& r1,
                                            uint32_t& r2, uint32_t& r3,
                                            uint32_t addr) {
    asm volatile("ldmatrix.sync.aligned.m8n8.x4.shared.b16 {%0,%1,%2,%3}, [%4];"
                 : "=r"(r0), "=r"(r1), "=r"(r2), "=r"(r3) : "r"(addr));
}
__device__ __forceinline__ void ldmatrix_x2(uint32_t& r0, uint32_t& r1,
                                            uint32_t addr) {
    asm volatile("ldmatrix.sync.aligned.m8n8.x2.shared.b16 {%0,%1}, [%2];"
                 : "=r"(r0), "=r"(r1) : "r"(addr));
}
__device__ __forceinline__ void mma16816(float* c, const uint32_t* a,
                                         const uint32_t* b) {
    asm volatile(
        "mma.sync.aligned.m16n8k16.row.col.f32.bf16.bf16.f32 "
        "{%0,%1,%2,%3}, {%4,%5,%6,%7}, {%8,%9}, {%0,%1,%2,%3};"
        : "+f"(c[0]), "+f"(c[1]), "+f"(c[2]), "+f"(c[3])
        : "r"(a[0]), "r"(a[1]), "r"(a[2]), "r"(a[3]), "r"(b[0]), "r"(b[1]));
}

// ---------------------------------------------------------------------------
// Kernel 1: split x into bf16 hi/lo
// ---------------------------------------------------------------------------
__global__ __launch_bounds__(256)
void convert_x_kernel(const float* __restrict__ x) {
    size_t i = (size_t)blockIdx.x * blockDim.x + threadIdx.x;   // one float4
    float4 v = reinterpret_cast<const float4*>(x)[i];

    __nv_bfloat16 h0 = __float2bfloat16(v.x);
    __nv_bfloat16 h1 = __float2bfloat16(v.y);
    __nv_bfloat16 h2 = __float2bfloat16(v.z);
    __nv_bfloat16 h3 = __float2bfloat16(v.w);
    __nv_bfloat16 l0 = __float2bfloat16(v.x - __bfloat162float(h0));
    __nv_bfloat16 l1 = __float2bfloat16(v.y - __bfloat162float(h1));
    __nv_bfloat16 l2 = __float2bfloat16(v.z - __bfloat162float(h2));
    __nv_bfloat16 l3 = __float2bfloat16(v.w - __bfloat162float(h3));

    __nv_bfloat162* Hp = reinterpret_cast<__nv_bfloat162*>(g_Ahi);
    __nv_bfloat162* Lp = reinterpret_cast<__nv_bfloat162*>(g_Alo);
    __nv_bfloat162 a; a.x = h0; a.y = h1;
    __nv_bfloat162 b; b.x = h2; b.y = h3;
    Hp[2 * i] = a; Hp[2 * i + 1] = b;
    a.x = l0; a.y = l1; b.x = l2; b.y = l3;
    Lp[2 * i] = a; Lp[2 * i + 1] = b;
}

// ---------------------------------------------------------------------------
// Kernel 2: transpose + split weights: g_WT[m][n*512+k] = W_m[k*512+n]
// ---------------------------------------------------------------------------
__global__ __launch_bounds__(256)
void convert_w_kernel(const float* __restrict__ kz,
                      const float* __restrict__ kr,
                      const float* __restrict__ kh) {
    const float* W = (blockIdx.y == 0) ? kz : (blockIdx.y == 1) ? kr : kh;
    int e = blockIdx.x * blockDim.x + threadIdx.x;   // 0 .. 512*512-1
    int n = e >> 9;
    int k = e & 511;
    float v = W[k * 512 + n];
    __nv_bfloat16 hi = __float2bfloat16(v);
    __nv_bfloat16 lo = __float2bfloat16(v - __bfloat162float(hi));
    g_WThi[blockIdx.y][e] = hi;
    g_WTlo[blockIdx.y][e] = lo;
}

// ---------------------------------------------------------------------------
// Kernel 3: bf16 GEMM via mma.sync.m16n8k16, 3-term hi/lo compensation.
// CTA tile 128x128, BK=32, 256 threads (8 warps: 2M x 4N, warp tile 64x32).
// SMEM rows padded to 80B (40 bf16) -> ldmatrix conflict-free.
// grid = (4, 256, 3): x=ntile, y=mtile, z=matrix.
// ---------------------------------------------------------------------------
#define LDS_ 40          // smem row stride in bf16 elements (80 bytes)

__global__ __launch_bounds__(256, 2)
void gemm_kernel() {
    __shared__ __align__(16) __nv_bfloat16 sA[2][128 * LDS_];
    __shared__ __align__(16) __nv_bfloat16 sB[2][128 * LDS_];

    const int tid  = threadIdx.x;
    const int lane = tid & 31;
    const int wid  = tid >> 5;
    const int wm   = (wid & 1) * 64;    // warp M offset in tile
    const int wn   = (wid >> 1) * 32;   // warp N offset in tile

    const int mat   = blockIdx.z;
    const int mBase = blockIdx.y * 128;
    const int nBase = blockIdx.x * 128;

    const __nv_bfloat16* Ap[3] = { g_Ahi + (size_t)mBase * D_,
                                   g_Alo + (size_t)mBase * D_,
                                   g_Ahi + (size_t)mBase * D_ };
    const __nv_bfloat16* Bp[3] = { g_WThi[mat] + (size_t)nBase * D_,
                                   g_WThi[mat] + (size_t)nBase * D_,
                                   g_WTlo[mat] + (size_t)nBase * D_ };
    float* C = g_proj[mat];

    // cp.async loader mapping: 512 16B-chunks per tile, 2 per thread
    const int lrow0 = tid >> 2;          // chunk c=tid      -> row
    const int lkc0  = tid & 3;           // 16B chunk in row (8 bf16)
    const int lrow1 = (tid + 256) >> 2;  // chunk c=tid+256
    const int lkc1  = lkc0;              // (tid+256)&3 == tid&3

    // ldmatrix per-lane offsets
    const int a_row = wm + (lane & 15);
    const int a_kb  = (lane >> 4) * 16;          // byte offset: 0 or 16
    const int b_row = wn + (lane & 7);
    const int b_kb  = ((lane >> 3) & 1) * 16;    // byte offset: 0 or 16

    float acc[4][4][4];
    #pragma unroll
    for (int i = 0; i < 4; ++i)
        #pragma unroll
        for (int j = 0; j < 4; ++j)
            #pragma unroll
            for (int e = 0; e < 4; ++e) acc[i][j][e] = 0.0f;

    auto load_tile = [&](int it, int buf) {
        const int pass = it >> 4;
        const int kk = (it & 15) * 32;
        const __nv_bfloat16* Ag = Ap[pass];
        const __nv_bfloat16* Bg = Bp[pass];
        uint32_t sa = smem_u32(&sA[buf][0]);
        uint32_t sbm = smem_u32(&sB[buf][0]);
        cp16(sa  + lrow0 * 80 + lkc0 * 16, Ag + (size_t)lrow0 * D_ + kk + lkc0 * 8);
        cp16(sa  + lrow1 * 80 + lkc1 * 16, Ag + (size_t)lrow1 * D_ + kk + lkc1 * 8);
        cp16(sbm + lrow0 * 80 + lkc0 * 16, Bg + (size_t)lrow0 * D_ + kk + lkc0 * 8);
        cp16(sbm + lrow1 * 80 + lkc1 * 16, Bg + (size_t)lrow1 * D_ + kk + lkc1 * 8);
    };

    constexpr int NIT = 48;   // 3 passes x 16 k-tiles
    load_tile(0, 0);
    CP_COMMIT();

    for (int it = 0; it < NIT; ++it) {
        const int buf = it & 1;
        if (it + 1 < NIT) {
            load_tile(it + 1, buf ^ 1);
            CP_COMMIT();
            CP_WAIT(1);
        } else {
            CP_WAIT(0);
        }
        __syncthreads();

        const uint32_t aBase = smem_u32(&sA[buf][0]) + a_row * 80 + a_kb;
        const uint32_t bBase = smem_u32(&sB[buf][0]) + b_row * 80 + b_kb;

        #pragma unroll
        for (int ks = 0; ks < 2; ++ks) {          // two k16 steps in BK=32
            uint32_t af[4][4], bfr[4][2];
            #pragma unroll
            for (int mt = 0; mt < 4; ++mt)
                ldmatrix_x4(af[mt][0], af[mt][1], af[mt][2], af[mt][3],
                            aBase + mt * 16 * 80 + ks * 32);
            #pragma unroll
            for (int nt = 0; nt < 4; ++nt)
                ldmatrix_x2(bfr[nt][0], bfr[nt][1],
                            bBase + nt * 8 * 80 + ks * 32);
            #pragma unroll
            for (int mt = 0; mt < 4; ++mt)
                #pragma unroll
                for (int nt = 0; nt < 4; ++nt)
                    mma16816(acc[mt][nt], af[mt], bfr[nt]);
        }
        __syncthreads();
    }

    // epilogue: c0,c1 at (row, col..col+1), c2,c3 at (row+8, ...)
    const int row0 = mBase + wm + (lane >> 2);
    const int col0 = nBase + wn + (lane & 3) * 2;
    #pragma unroll
    for (int mt = 0; mt < 4; ++mt) {
        #pragma unroll
        for (int nt = 0; nt < 4; ++nt) {
            float* p = C + (size_t)(row0 + mt * 16) * H_ + col0 + nt * 8;
            float2 v0 = make_float2(acc[mt][nt][0], acc[mt][nt][1]);
            float2 v1 = make_float2(acc[mt][nt][2], acc[mt][nt][3]);
            *reinterpret_cast<float2*>(p) = v0;
            *reinterpret_cast<float2*>(p + 8 * H_) = v1;
        }
    }
}

// ---------------------------------------------------------------------------
// Kernel 4: diagonal recurrence scan with depth-8 register prefetch ring.
// ---------------------------------------------------------------------------
__global__ __launch_bounds__(128)
void scan_kernel(const float* __restrict__ h0,
                 const float* __restrict__ mz, const float* __restrict__ mr,
                 const float* __restrict__ bz, const float* __restrict__ br,
                 float* __restrict__ out)
{
    const int gid = blockIdx.x * 128 + threadIdx.x;   // 0 .. B*H-1
    const int b = gid >> 9;
    const int h = gid & 511;

    float hv = h0[gid];
    const float mzv = mz[h];
    const float mrv = mr[h];
    const float bzv = bz[h];
    const float brv = br[h];

    const size_t base = (size_t)b * T_ * H_ + h;
    const float* xz = g_proj[0] + base;
    const float* xr = g_proj[1] + base;
    const float* xh = g_proj[2] + base;
    float* o = out + base;

    float vz[8], vr[8], vh[8];
    #pragma unroll
    for (int i = 0; i < 8; ++i) {
        size_t off = (size_t)i * H_;
        vz[i] = __ldcs(xz + off);
        vr[i] = __ldcs(xr + off);
        vh[i] = __ldcs(xh + off);
    }

    for (int t0 = 0; t0 < T_; t0 += 8) {
        #pragma unroll
        for (int i = 0; i < 8; ++i) {
            const float az = vz[i] + bzv;
            const float ar = vr[i] + brv;
            const float ah = vh[i];

            // prefetch t0+i+8 (reads into the padded tail on the last block)
            const size_t poff = (size_t)(t0 + i + 8) * H_;
            vz[i] = __ldcs(xz + poff);
            vr[i] = __ldcs(xr + poff);
            vh[i] = __ldcs(xh + poff);

            const float r  = tanhf(fmaf(hv, mrv, ar)) + 1.0f;
            const float z  = 1.0f / (1.0f + __expf(-fmaf(hv, mzv, az)));
            const float ht = tanhf(fmaf(r, hv, ah));
            hv = fmaf(z, hv, (1.0f - z) * ht);

            __stcs(o + (size_t)(t0 + i) * H_, hv);
        }
    }
}

// ---------------------------------------------------------------------------
extern "C" void kernel_launch(void* const* d_in, const int* in_sizes, int n_in,
                              void* d_out, int out_size)
{
    const float* x  = (const float*)d_in[0];
    const float* h0 = (const float*)d_in[1];
    const float* kz = (const float*)d_in[2];
    const float* kr = (const float*)d_in[3];
    const float* kh = (const float*)d_in[4];
    const float* mz = (const float*)d_in[5];
    const float* mr = (const float*)d_in[6];
    const float* bz = (const float*)d_in[7];
    const float* br = (const float*)d_in[8];
    float* out = (float*)d_out;

    // split x into bf16 hi/lo: 16.7M elems / 4 per thread
    convert_x_kernel<<<(MTOT * D_ / 4) / 256, 256>>>(x);
    // transpose + split weights
    convert_w_kernel<<<dim3((H_ * D_) / 256, 3), 256>>>(kz, kr, kh);
    // 3 projections via mma.sync bf16 (3-term compensated)
    gemm_kernel<<<dim3(H_ / 128, MTOT / 128, 3), 256>>>();
    // recurrence
    scan_kernel<<<(B_ * H_) / 128, 128>>>(h0, mz, mr, bz, br, out);
}

// round 5
// speedup vs baseline: 2.5671x; 1.0984x over previous
#include <cuda_runtime.h>
#include <cuda_bf16.h>
#include <cstdint>
#include <math.h>

#define B_   64
#define T_   512
#define D_   512
#define H_   512
#define MTOT (B_ * T_)          // 32768 GEMM rows

// ---------------------------------------------------------------------------
// Scratch (static __device__ — allocation-guard safe)
// ---------------------------------------------------------------------------
// projections xz, xr, xh (fp32) + 16-step pad for the scan prefetch ring.
__device__ float g_proj[3][(size_t)MTOT * H_ + 16 * H_];
// bf16 hi/lo split of x
__device__ __nv_bfloat16 g_Ahi[(size_t)MTOT * D_];
__device__ __nv_bfloat16 g_Alo[(size_t)MTOT * D_];
// bf16 hi/lo split of W^T (stored [N][K] K-major)
__device__ __nv_bfloat16 g_WThi[3][H_ * D_];
__device__ __nv_bfloat16 g_WTlo[3][H_ * D_];

// ---------------------------------------------------------------------------
// helpers
// ---------------------------------------------------------------------------
__device__ __forceinline__ uint32_t smem_u32(const void* p) {
    return (uint32_t)__cvta_generic_to_shared(p);
}

__device__ __forceinline__ void cp16(uint32_t dst, const void* src) {
    asm volatile("cp.async.cg.shared.global [%0], [%1], 16;"
                 :: "r"(dst), "l"(src) : "memory");
}
#define CP_COMMIT() asm volatile("cp.async.commit_group;" ::: "memory")
#define CP_WAIT(n)  asm volatile("cp.async.wait_group %0;" :: "n"(n) : "memory")

__device__ __forceinline__ void ldmatrix_x4(uint32_t& r0, uint32_t& r1,
                                            uint32_t& r2, uint32_t& r3,
                                            uint32_t addr) {
    asm volatile("ldmatrix.sync.aligned.m8n8.x4.shared.b16 {%0,%1,%2,%3}, [%4];"
                 : "=r"(r0), "=r"(r1), "=r"(r2), "=r"(r3) : "r"(addr));
}
__device__ __forceinline__ void mma16816(float* c, const uint32_t* a,
                                         const uint32_t* b) {
    asm volatile(
        "mma.sync.aligned.m16n8k16.row.col.f32.bf16.bf16.f32 "
        "{%0,%1,%2,%3}, {%4,%5,%6,%7}, {%8,%9}, {%0,%1,%2,%3};"
        : "+f"(c[0]), "+f"(c[1]), "+f"(c[2]), "+f"(c[3])
        : "r"(a[0]), "r"(a[1]), "r"(a[2]), "r"(a[3]), "r"(b[0]), "r"(b[1]));
}

// ---------------------------------------------------------------------------
// Kernel 1: split x into bf16 hi/lo
// ---------------------------------------------------------------------------
__global__ __launch_bounds__(256)
void convert_x_kernel(const float* __restrict__ x) {
    size_t i = (size_t)blockIdx.x * blockDim.x + threadIdx.x;   // one float4
    float4 v = reinterpret_cast<const float4*>(x)[i];

    __nv_bfloat16 h0 = __float2bfloat16(v.x);
    __nv_bfloat16 h1 = __float2bfloat16(v.y);
    __nv_bfloat16 h2 = __float2bfloat16(v.z);
    __nv_bfloat16 h3 = __float2bfloat16(v.w);
    __nv_bfloat16 l0 = __float2bfloat16(v.x - __bfloat162float(h0));
    __nv_bfloat16 l1 = __float2bfloat16(v.y - __bfloat162float(h1));
    __nv_bfloat16 l2 = __float2bfloat16(v.z - __bfloat162float(h2));
    __nv_bfloat16 l3 = __float2bfloat16(v.w - __bfloat162float(h3));

    __nv_bfloat162* Hp = reinterpret_cast<__nv_bfloat162*>(g_Ahi);
    __nv_bfloat162* Lp = reinterpret_cast<__nv_bfloat162*>(g_Alo);
    __nv_bfloat162 a; a.x = h0; a.y = h1;
    __nv_bfloat162 b; b.x = h2; b.y = h3;
    Hp[2 * i] = a; Hp[2 * i + 1] = b;
    a.x = l0; a.y = l1; b.x = l2; b.y = l3;
    Lp[2 * i] = a; Lp[2 * i + 1] = b;
}

// ---------------------------------------------------------------------------
// Kernel 2: transpose + split weights: g_WT[m][n*512+k] = W_m[k*512+n]
// ---------------------------------------------------------------------------
__global__ __launch_bounds__(256)
void convert_w_kernel(const float* __restrict__ kz,
                      const float* __restrict__ kr,
                      const float* __restrict__ kh) {
    const float* W = (blockIdx.y == 0) ? kz : (blockIdx.y == 1) ? kr : kh;
    int e = blockIdx.x * blockDim.x + threadIdx.x;   // 0 .. 512*512-1
    int n = e >> 9;
    int k = e & 511;
    float v = W[k * 512 + n];
    __nv_bfloat16 hi = __float2bfloat16(v);
    __nv_bfloat16 lo = __float2bfloat16(v - __bfloat162float(hi));
    g_WThi[blockIdx.y][e] = hi;
    g_WTlo[blockIdx.y][e] = lo;
}

// ---------------------------------------------------------------------------
// Kernel 3: bf16 GEMM via mma.sync.m16n8k16, 3-term hi/lo compensation.
// CTA tile 128x256, BK=32, 256 threads (8 warps: 2M x 4N, warp tile 64x64).
// 4-stage cp.async pipeline, ONE __syncthreads per iteration.
// SMEM rows padded to 80B -> ldmatrix conflict-free.
// grid = (2, 256, 3): x=ntile, y=mtile, z=matrix.
// ---------------------------------------------------------------------------
#define A_STAGE   (128 * 80)                 // 10240 B
#define B_STAGE   (256 * 80)                 // 20480 B
#define STAGE_B   (A_STAGE + B_STAGE)        // 30720 B
#define GEMM_SMEM (4 * STAGE_B)              // 122880 B

__global__ __launch_bounds__(256, 1)
void gemm_kernel() {
    extern __shared__ __align__(128) char dsmem[];
    const uint32_t sbase = smem_u32(dsmem);

    const int tid  = threadIdx.x;
    const int lane = tid & 31;
    const int wid  = tid >> 5;
    const int wm   = (wid & 1) * 64;    // warp M offset in tile
    const int wn   = (wid >> 1) * 64;   // warp N offset in tile

    const int mat   = blockIdx.z;
    const int mBase = blockIdx.y * 128;
    const int nBase = blockIdx.x * 256;

    const __nv_bfloat16* Ahi = g_Ahi + (size_t)mBase * D_;
    const __nv_bfloat16* Alo = g_Alo + (size_t)mBase * D_;
    const __nv_bfloat16* Whi = g_WThi[mat] + (size_t)nBase * D_;
    const __nv_bfloat16* Wlo = g_WTlo[mat] + (size_t)nBase * D_;
    float* C = g_proj[mat];

    // loader mapping (16B chunks, 4 chunks per 32-bf16 row segment)
    const int lrow = tid >> 2;       // base row (0..63), stepped by +64
    const int lkc  = tid & 3;        // 16B chunk within row

    // ldmatrix per-lane offsets
    const int a_off = (wm + (lane & 15)) * 80 + (lane >> 4) * 16;
    const int b_off = (wn + (lane & 7) + ((lane >> 4) & 1) * 8) * 80
                    + ((lane >> 3) & 1) * 16;

    float acc[4][8][4];
    #pragma unroll
    for (int i = 0; i < 4; ++i)
        #pragma unroll
        for (int j = 0; j < 8; ++j)
            #pragma unroll
            for (int e = 0; e < 4; ++e) acc[i][j][e] = 0.0f;

    auto load_tile = [&](int j) {
        const int pass = j >> 4;             // 0:hi*hi 1:lo*hi 2:hi*lo
        const int kk = (j & 15) * 32;
        const __nv_bfloat16* Ag = (pass == 1) ? Alo : Ahi;
        const __nv_bfloat16* Bg = (pass == 2) ? Wlo : Whi;
        const uint32_t sa = sbase + (j & 3) * STAGE_B;
        const uint32_t sb = sa + A_STAGE;
        // A: 128 rows x 4 chunks = 512 chunks, 2 per thread
        #pragma unroll
        for (int i = 0; i < 2; ++i) {
            int row = lrow + i * 64;
            cp16(sa + row * 80 + lkc * 16, Ag + (size_t)row * D_ + kk + lkc * 8);
        }
        // B: 256 rows x 4 chunks = 1024 chunks, 4 per thread
        #pragma unroll
        for (int i = 0; i < 4; ++i) {
            int row = lrow + i * 64;
            cp16(sb + row * 80 + lkc * 16, Bg + (size_t)row * D_ + kk + lkc * 8);
        }
    };

    constexpr int NIT = 48;   // 3 passes x 16 k-tiles
    load_tile(0);
    CP_COMMIT();
    load_tile(1);
    CP_COMMIT();

    for (int it = 0; it < NIT; ++it) {
        // prefetch 2 ahead into buffer (it+2)&3 == (it-2)&3 — its last
        // compute finished before the sync of iteration it-1: hazard-free.
        if (it + 2 < NIT) load_tile(it + 2);
        CP_COMMIT();               // empty commits at tail keep wait math uniform
        CP_WAIT(2);                // buffer (it)&3 is resident
        __syncthreads();           // make all warps' cp.async data visible

        const uint32_t sa = sbase + (it & 3) * STAGE_B;
        const uint32_t aB = sa + a_off;
        const uint32_t bB = sa + A_STAGE + b_off;

        #pragma unroll
        for (int ks = 0; ks < 2; ++ks) {          // two k16 steps in BK=32
            uint32_t af[4][4], bq[4][4];
            #pragma unroll
            for (int mt = 0; mt < 4; ++mt)
                ldmatrix_x4(af[mt][0], af[mt][1], af[mt][2], af[mt][3],
                            aB + mt * 16 * 80 + ks * 32);
            #pragma unroll
            for (int np = 0; np < 4; ++np)        // each x4 = two n8 b-frags
                ldmatrix_x4(bq[np][0], bq[np][1], bq[np][2], bq[np][3],
                            bB + np * 16 * 80 + ks * 32);
            #pragma unroll
            for (int mt = 0; mt < 4; ++mt)
                #pragma unroll
                for (int nt = 0; nt < 8; ++nt)
                    mma16816(acc[mt][nt], af[mt], &bq[nt >> 1][(nt & 1) * 2]);
        }
    }

    // epilogue
    const int row0 = mBase + wm + (lane >> 2);
    const int col0 = nBase + wn + (lane & 3) * 2;
    #pragma unroll
    for (int mt = 0; mt < 4; ++mt) {
        #pragma unroll
        for (int nt = 0; nt < 8; ++nt) {
            float* p = C + (size_t)(row0 + mt * 16) * H_ + col0 + nt * 8;
            *reinterpret_cast<float2*>(p) =
                make_float2(acc[mt][nt][0], acc[mt][nt][1]);
            *reinterpret_cast<float2*>(p + 8 * H_) =
                make_float2(acc[mt][nt][2], acc[mt][nt][3]);
        }
    }
}

// ---------------------------------------------------------------------------
// Kernel 4: diagonal recurrence scan, depth-16 register prefetch ring.
// ---------------------------------------------------------------------------
__global__ __launch_bounds__(128)
void scan_kernel(const float* __restrict__ h0,
                 const float* __restrict__ mz, const float* __restrict__ mr,
                 const float* __restrict__ bz, const float* __restrict__ br,
                 float* __restrict__ out)
{
    const int gid = blockIdx.x * 128 + threadIdx.x;   // 0 .. B*H-1
    const int b = gid >> 9;
    const int h = gid & 511;

    float hv = h0[gid];
    const float mzv = mz[h];
    const float mrv = mr[h];
    const float bzv = bz[h];
    const float brv = br[h];

    const size_t base = (size_t)b * T_ * H_ + h;
    const float* xz = g_proj[0] + base;
    const float* xr = g_proj[1] + base;
    const float* xh = g_proj[2] + base;
    float* o = out + base;

    float vz[16], vr[16], vh[16];
    #pragma unroll
    for (int i = 0; i < 16; ++i) {
        size_t off = (size_t)i * H_;
        vz[i] = __ldcs(xz + off);
        vr[i] = __ldcs(xr + off);
        vh[i] = __ldcs(xh + off);
    }

    for (int t0 = 0; t0 < T_; t0 += 16) {
        #pragma unroll
        for (int i = 0; i < 16; ++i) {
            const float az = vz[i] + bzv;
            const float ar = vr[i] + brv;
            const float ah = vh[i];

            // prefetch t0+i+16 (reads into the padded tail on the last block)
            const size_t poff = (size_t)(t0 + i + 16) * H_;
            vz[i] = __ldcs(xz + poff);
            vr[i] = __ldcs(xr + poff);
            vh[i] = __ldcs(xh + poff);

            const float r  = tanhf(fmaf(hv, mrv, ar)) + 1.0f;
            const float z  = 1.0f / (1.0f + __expf(-fmaf(hv, mzv, az)));
            const float ht = tanhf(fmaf(r, hv, ah));
            hv = fmaf(z, hv, (1.0f - z) * ht);

            __stcs(o + (size_t)(t0 + i) * H_, hv);
        }
    }
}

// ---------------------------------------------------------------------------
extern "C" void kernel_launch(void* const* d_in, const int* in_sizes, int n_in,
                              void* d_out, int out_size)
{
    const float* x  = (const float*)d_in[0];
    const float* h0 = (const float*)d_in[1];
    const float* kz = (const float*)d_in[2];
    const float* kr = (const float*)d_in[3];
    const float* kh = (const float*)d_in[4];
    const float* mz = (const float*)d_in[5];
    const float* mr = (const float*)d_in[6];
    const float* bz = (const float*)d_in[7];
    const float* br = (const float*)d_in[8];
    float* out = (float*)d_out;

    cudaFuncSetAttribute(gemm_kernel,
                         cudaFuncAttributeMaxDynamicSharedMemorySize,
                         GEMM_SMEM);

    // split x into bf16 hi/lo
    convert_x_kernel<<<(MTOT * D_ / 4) / 256, 256>>>(x);
    // transpose + split weights
    convert_w_kernel<<<dim3((H_ * D_) / 256, 3), 256>>>(kz, kr, kh);
    // 3 projections via mma.sync bf16 (3-term compensated)
    gemm_kernel<<<dim3(H_ / 256, MTOT / 128, 3), 256, GEMM_SMEM>>>();
    // recurrence
    scan_kernel<<<(B_ * H_) / 128, 128>>>(h0, mz, mr, bz, br, out);
}

// round 6
// speedup vs baseline: 3.8194x; 1.4878x over previous
#include <cuda_runtime.h>
#include <cuda_fp16.h>
#include <cstdint>
#include <math.h>

#define B_   64
#define T_   512
#define D_   512
#define H_   512
#define MTOT (B_ * T_)          // 32768 GEMM rows

// ---------------------------------------------------------------------------
// Scratch (static __device__ — allocation-guard safe)
// ---------------------------------------------------------------------------
// projections xz, xr, xh (fp32) + 16-step pad for the scan prefetch ring.
__device__ float g_proj[3][(size_t)MTOT * H_ + 16 * H_];
// fp16 hi/lo split of x
__device__ __half g_Ahi[(size_t)MTOT * D_];
__device__ __half g_Alo[(size_t)MTOT * D_];
// fp16 W^T (stored [N][K] K-major); no lo needed for 2-term scheme
__device__ __half g_WT[3][H_ * D_];

// ---------------------------------------------------------------------------
// helpers
// ---------------------------------------------------------------------------
__device__ __forceinline__ uint32_t smem_u32(const void* p) {
    return (uint32_t)__cvta_generic_to_shared(p);
}

__device__ __forceinline__ void cp16(uint32_t dst, const void* src) {
    asm volatile("cp.async.cg.shared.global [%0], [%1], 16;"
                 :: "r"(dst), "l"(src) : "memory");
}
#define CP_COMMIT() asm volatile("cp.async.commit_group;" ::: "memory")
#define CP_WAIT(n)  asm volatile("cp.async.wait_group %0;" :: "n"(n) : "memory")

__device__ __forceinline__ void ldmatrix_x4(uint32_t& r0, uint32_t& r1,
                                            uint32_t& r2, uint32_t& r3,
                                            uint32_t addr) {
    asm volatile("ldmatrix.sync.aligned.m8n8.x4.shared.b16 {%0,%1,%2,%3}, [%4];"
                 : "=r"(r0), "=r"(r1), "=r"(r2), "=r"(r3) : "r"(addr));
}
__device__ __forceinline__ void mma16816(float* c, const uint32_t* a,
                                         const uint32_t* b) {
    asm volatile(
        "mma.sync.aligned.m16n8k16.row.col.f32.f16.f16.f32 "
        "{%0,%1,%2,%3}, {%4,%5,%6,%7}, {%8,%9}, {%0,%1,%2,%3};"
        : "+f"(c[0]), "+f"(c[1]), "+f"(c[2]), "+f"(c[3])
        : "r"(a[0]), "r"(a[1]), "r"(a[2]), "r"(a[3]), "r"(b[0]), "r"(b[1]));
}

// fast tanh: 1 - 2/(e^{2x}+1). MUFU-based, ~1e-6 abs error, saturates correctly.
__device__ __forceinline__ float tanh_fast(float x) {
    float e = __expf(2.0f * x);
    return 1.0f - 2.0f * __fdividef(1.0f, e + 1.0f);
}

// ---------------------------------------------------------------------------
// Kernel 1: split x into fp16 hi/lo
// ---------------------------------------------------------------------------
__global__ __launch_bounds__(256)
void convert_x_kernel(const float* __restrict__ x) {
    size_t i = (size_t)blockIdx.x * blockDim.x + threadIdx.x;   // one float4
    float4 v = reinterpret_cast<const float4*>(x)[i];

    __half h0 = __float2half_rn(v.x);
    __half h1 = __float2half_rn(v.y);
    __half h2 = __float2half_rn(v.z);
    __half h3 = __float2half_rn(v.w);
    __half l0 = __float2half_rn(v.x - __half2float(h0));
    __half l1 = __float2half_rn(v.y - __half2float(h1));
    __half l2 = __float2half_rn(v.z - __half2float(h2));
    __half l3 = __float2half_rn(v.w - __half2float(h3));

    __half2* Hp = reinterpret_cast<__half2*>(g_Ahi);
    __half2* Lp = reinterpret_cast<__half2*>(g_Alo);
    Hp[2 * i]     = __halves2half2(h0, h1);
    Hp[2 * i + 1] = __halves2half2(h2, h3);
    Lp[2 * i]     = __halves2half2(l0, l1);
    Lp[2 * i + 1] = __halves2half2(l2, l3);
}

// ---------------------------------------------------------------------------
// Kernel 2: transpose weights to fp16 [N][K]: g_WT[m][n*512+k] = W_m[k*512+n]
// ---------------------------------------------------------------------------
__global__ __launch_bounds__(256)
void convert_w_kernel(const float* __restrict__ kz,
                      const float* __restrict__ kr,
                      const float* __restrict__ kh) {
    const float* W = (blockIdx.y == 0) ? kz : (blockIdx.y == 1) ? kr : kh;
    int e = blockIdx.x * blockDim.x + threadIdx.x;   // 0 .. 512*512-1
    int n = e >> 9;
    int k = e & 511;
    g_WT[blockIdx.y][e] = __float2half_rn(W[k * 512 + n]);
}

// ---------------------------------------------------------------------------
// Kernel 3: fp16 GEMM via mma.sync.m16n8k16, 2-term A-split compensation.
// C = A_hi*W + A_lo*W, both terms share the SAME B tile per k-tile.
// CTA tile 128x256, BK=32, 256 threads (8 warps: 2M x 4N, warp tile 64x64).
// 4-stage cp.async pipeline, one __syncthreads per iteration, NIT=16.
// SMEM rows padded to 80B -> conflict-free cp.async stores + ldmatrix.
// grid = (6, 256): x = mat*2 + ntile (mat/ntile co-resident per mtile for
// L2 reuse of A), y = mtile.
// ---------------------------------------------------------------------------
#define A_STAGE   (128 * 80)                     // 10240 B (one A half-tile)
#define B_STAGE   (256 * 80)                     // 20480 B
#define STAGE_B   (2 * A_STAGE + B_STAGE)        // 40960 B (Ahi, Alo, B)
#define GEMM_SMEM (4 * STAGE_B)                  // 163840 B

__global__ __launch_bounds__(256, 1)
void gemm_kernel() {
    extern __shared__ __align__(128) char dsmem[];
    const uint32_t sbase = smem_u32(dsmem);

    const int tid  = threadIdx.x;
    const int lane = tid & 31;
    const int wid  = tid >> 5;
    const int wm   = (wid & 1) * 64;    // warp M offset in tile
    const int wn   = (wid >> 1) * 64;   // warp N offset in tile

    const int mat   = blockIdx.x >> 1;
    const int nBase = (blockIdx.x & 1) * 256;
    const int mBase = blockIdx.y * 128;

    const __half* Ahi = g_Ahi + (size_t)mBase * D_;
    const __half* Alo = g_Alo + (size_t)mBase * D_;
    const __half* Wp  = g_WT[mat] + (size_t)nBase * D_;
    float* C = g_proj[mat];

    // loader mapping: rows of 32 halfs = 64B = 4 x 16B chunks
    const int lrow = tid >> 2;       // base row (0..63), stepped by +64
    const int lkc  = tid & 3;        // 16B chunk within row

    // ldmatrix per-lane offsets (row stride 80B; two 8x8 k-halves 16B apart)
    const int a_off = (wm + (lane & 15)) * 80 + (lane >> 4) * 16;
    const int b_off = (wn + (lane & 7) + ((lane >> 4) & 1) * 8) * 80
                    + ((lane >> 3) & 1) * 16;

    float acc[4][8][4];
    #pragma unroll
    for (int i = 0; i < 4; ++i)
        #pragma unroll
        for (int j = 0; j < 8; ++j)
            #pragma unroll
            for (int e = 0; e < 4; ++e) acc[i][j][e] = 0.0f;

    auto load_tile = [&](int j) {                // j = k-tile index 0..15
        const int kk = j * 32;
        const uint32_t sa = sbase + (j & 3) * STAGE_B;
        #pragma unroll
        for (int i = 0; i < 2; ++i) {            // A_hi + A_lo: 2 chunks each
            int row = lrow + i * 64;
            cp16(sa + row * 80 + lkc * 16,
                 Ahi + (size_t)row * D_ + kk + lkc * 8);
            cp16(sa + A_STAGE + row * 80 + lkc * 16,
                 Alo + (size_t)row * D_ + kk + lkc * 8);
        }
        #pragma unroll
        for (int i = 0; i < 4; ++i) {            // B: 4 chunks
            int row = lrow + i * 64;
            cp16(sa + 2 * A_STAGE + row * 80 + lkc * 16,
                 Wp + (size_t)row * D_ + kk + lkc * 8);
        }
    };

    constexpr int NIT = 16;   // 512 / BK
    load_tile(0);
    CP_COMMIT();
    load_tile(1);
    CP_COMMIT();

    for (int it = 0; it < NIT; ++it) {
        // prefetch 2 ahead into buffer (it+2)&3 == (it-2)&3 — its last
        // compute finished before the sync of iteration it-1: hazard-free.
        if (it + 2 < NIT) load_tile(it + 2);
        CP_COMMIT();               // empty commits at tail keep wait math uniform
        CP_WAIT(2);                // buffer (it)&3 is resident
        __syncthreads();

        const uint32_t sa = sbase + (it & 3) * STAGE_B;
        const uint32_t aHiB = sa + a_off;
        const uint32_t aLoB = sa + A_STAGE + a_off;
        const uint32_t bB   = sa + 2 * A_STAGE + b_off;

        #pragma unroll
        for (int ks = 0; ks < 2; ++ks) {          // two k16 steps in BK=32
            uint32_t ah[4][4], al[4][4], bq[4][4];
            #pragma unroll
            for (int mt = 0; mt < 4; ++mt)
                ldmatrix_x4(ah[mt][0], ah[mt][1], ah[mt][2], ah[mt][3],
                            aHiB + mt * 16 * 80 + ks * 32);
            #pragma unroll
            for (int mt = 0; mt < 4; ++mt)
                ldmatrix_x4(al[mt][0], al[mt][1], al[mt][2], al[mt][3],
                            aLoB + mt * 16 * 80 + ks * 32);
            #pragma unroll
            for (int np = 0; np < 4; ++np)        // each x4 = two n8 b-frags
                ldmatrix_x4(bq[np][0], bq[np][1], bq[np][2], bq[np][3],
                            bB + np * 16 * 80 + ks * 32);
            #pragma unroll
            for (int mt = 0; mt < 4; ++mt)
                #pragma unroll
                for (int nt = 0; nt < 8; ++nt)
                    mma16816(acc[mt][nt], ah[mt], &bq[nt >> 1][(nt & 1) * 2]);
            #pragma unroll
            for (int mt = 0; mt < 4; ++mt)
                #pragma unroll
                for (int nt = 0; nt < 8; ++nt)
                    mma16816(acc[mt][nt], al[mt], &bq[nt >> 1][(nt & 1) * 2]);
        }
    }

    // epilogue
    const int row0 = mBase + wm + (lane >> 2);
    const int col0 = nBase + wn + (lane & 3) * 2;
    #pragma unroll
    for (int mt = 0; mt < 4; ++mt) {
        #pragma unroll
        for (int nt = 0; nt < 8; ++nt) {
            float* p = C + (size_t)(row0 + mt * 16) * H_ + col0 + nt * 8;
            *reinterpret_cast<float2*>(p) =
                make_float2(acc[mt][nt][0], acc[mt][nt][1]);
            *reinterpret_cast<float2*>(p + 8 * H_) =
                make_float2(acc[mt][nt][2], acc[mt][nt][3]);
        }
    }
}

// ---------------------------------------------------------------------------
// Kernel 4: diagonal recurrence scan, depth-16 register prefetch ring,
// MUFU-based tanh/sigmoid (cuts ~71 -> ~30 instr/step; chain was ILP-bound).
// ---------------------------------------------------------------------------
__global__ __launch_bounds__(128)
void scan_kernel(const float* __restrict__ h0,
                 const float* __restrict__ mz, const float* __restrict__ mr,
                 const float* __restrict__ bz, const float* __restrict__ br,
                 float* __restrict__ out)
{
    const int gid = blockIdx.x * 128 + threadIdx.x;   // 0 .. B*H-1
    const int b = gid >> 9;
    const int h = gid & 511;

    float hv = h0[gid];
    const float mzv = mz[h];
    const float mrv = mr[h];
    const float bzv = bz[h];
    const float brv = br[h];

    const size_t base = (size_t)b * T_ * H_ + h;
    const float* xz = g_proj[0] + base;
    const float* xr = g_proj[1] + base;
    const float* xh = g_proj[2] + base;
    float* o = out + base;

    float vz[16], vr[16], vh[16];
    #pragma unroll
    for (int i = 0; i < 16; ++i) {
        size_t off = (size_t)i * H_;
        vz[i] = __ldcs(xz + off);
        vr[i] = __ldcs(xr + off);
        vh[i] = __ldcs(xh + off);
    }

    for (int t0 = 0; t0 < T_; t0 += 16) {
        #pragma unroll
        for (int i = 0; i < 16; ++i) {
            const float az = vz[i] + bzv;
            const float ar = vr[i] + brv;
            const float ah = vh[i];

            // prefetch t0+i+16 (reads into the padded tail on the last block)
            const size_t poff = (size_t)(t0 + i + 16) * H_;
            vz[i] = __ldcs(xz + poff);
            vr[i] = __ldcs(xr + poff);
            vh[i] = __ldcs(xh + poff);

            const float r  = tanh_fast(fmaf(hv, mrv, ar)) + 1.0f;
            const float z  = __fdividef(1.0f, 1.0f + __expf(-fmaf(hv, mzv, az)));
            const float ht = tanh_fast(fmaf(r, hv, ah));
            hv = fmaf(z, hv, (1.0f - z) * ht);

            __stcs(o + (size_t)(t0 + i) * H_, hv);
        }
    }
}

// ---------------------------------------------------------------------------
extern "C" void kernel_launch(void* const* d_in, const int* in_sizes, int n_in,
                              void* d_out, int out_size)
{
    const float* x  = (const float*)d_in[0];
    const float* h0 = (const float*)d_in[1];
    const float* kz = (const float*)d_in[2];
    const float* kr = (const float*)d_in[3];
    const float* kh = (const float*)d_in[4];
    const float* mz = (const float*)d_in[5];
    const float* mr = (const float*)d_in[6];
    const float* bz = (const float*)d_in[7];
    const float* br = (const float*)d_in[8];
    float* out = (float*)d_out;

    cudaFuncSetAttribute(gemm_kernel,
                         cudaFuncAttributeMaxDynamicSharedMemorySize,
                         GEMM_SMEM);

    // split x into fp16 hi/lo
    convert_x_kernel<<<(MTOT * D_ / 4) / 256, 256>>>(x);
    // transpose weights to fp16 [N][K]
    convert_w_kernel<<<dim3((H_ * D_) / 256, 3), 256>>>(kz, kr, kh);
    // 3 projections via mma.sync fp16 (2-term A-split compensated)
    gemm_kernel<<<dim3(6, MTOT / 128), 256, GEMM_SMEM>>>();
    // recurrence
    scan_kernel<<<(B_ * H_) / 128, 128>>>(h0, mz, mr, bz, br, out);
}

// round 7
// speedup vs baseline: 5.0407x; 1.3198x over previous
#include <cuda_runtime.h>
#include <cuda_fp16.h>
#include <cstdint>
#include <math.h>

#define B_   64
#define T_   512
#define D_   512
#define H_   512
#define MTOT (B_ * T_)          // 32768 GEMM rows

// ---------------------------------------------------------------------------
// Scratch (static __device__ — allocation-guard safe)
// ---------------------------------------------------------------------------
// projections xz, xr, xh (fp32) + 16-step pad for the scan prefetch ring.
__device__ float g_proj[3][(size_t)MTOT * H_ + 16 * H_];
// fp16 x
__device__ __half g_A[(size_t)MTOT * D_];
// fp16 W^T (stored [N][K] K-major)
__device__ __half g_WT[3][H_ * D_];

// ---------------------------------------------------------------------------
// helpers
// ---------------------------------------------------------------------------
__device__ __forceinline__ uint32_t smem_u32(const void* p) {
    return (uint32_t)__cvta_generic_to_shared(p);
}

__device__ __forceinline__ void cp16(uint32_t dst, const void* src) {
    asm volatile("cp.async.cg.shared.global [%0], [%1], 16;"
                 :: "r"(dst), "l"(src) : "memory");
}
#define CP_COMMIT() asm volatile("cp.async.commit_group;" ::: "memory")
#define CP_WAIT(n)  asm volatile("cp.async.wait_group %0;" :: "n"(n) : "memory")

__device__ __forceinline__ void ldmatrix_x4(uint32_t& r0, uint32_t& r1,
                                            uint32_t& r2, uint32_t& r3,
                                            uint32_t addr) {
    asm volatile("ldmatrix.sync.aligned.m8n8.x4.shared.b16 {%0,%1,%2,%3}, [%4];"
                 : "=r"(r0), "=r"(r1), "=r"(r2), "=r"(r3) : "r"(addr));
}
__device__ __forceinline__ void mma16816(float* c, const uint32_t* a,
                                         const uint32_t* b) {
    asm volatile(
        "mma.sync.aligned.m16n8k16.row.col.f32.f16.f16.f32 "
        "{%0,%1,%2,%3}, {%4,%5,%6,%7}, {%8,%9}, {%0,%1,%2,%3};"
        : "+f"(c[0]), "+f"(c[1]), "+f"(c[2]), "+f"(c[3])
        : "r"(a[0]), "r"(a[1]), "r"(a[2]), "r"(a[3]), "r"(b[0]), "r"(b[1]));
}

// fast tanh: 1 - 2/(e^{2x}+1). MUFU-based, ~1e-6 abs error, saturates correctly.
__device__ __forceinline__ float tanh_fast(float x) {
    float e = __expf(2.0f * x);
    return 1.0f - 2.0f * __fdividef(1.0f, e + 1.0f);
}

// ---------------------------------------------------------------------------
// Kernel 1: convert x to fp16
// ---------------------------------------------------------------------------
__global__ __launch_bounds__(256)
void convert_x_kernel(const float* __restrict__ x) {
    size_t i = (size_t)blockIdx.x * blockDim.x + threadIdx.x;   // one float4
    float4 v = reinterpret_cast<const float4*>(x)[i];
    __half2* Hp = reinterpret_cast<__half2*>(g_A);
    Hp[2 * i]     = __halves2half2(__float2half_rn(v.x), __float2half_rn(v.y));
    Hp[2 * i + 1] = __halves2half2(__float2half_rn(v.z), __float2half_rn(v.w));
}

// ---------------------------------------------------------------------------
// Kernel 2: transpose weights to fp16 [N][K]: g_WT[m][n*512+k] = W_m[k*512+n]
// ---------------------------------------------------------------------------
__global__ __launch_bounds__(256)
void convert_w_kernel(const float* __restrict__ kz,
                      const float* __restrict__ kr,
                      const float* __restrict__ kh) {
    const float* W = (blockIdx.y == 0) ? kz : (blockIdx.y == 1) ? kr : kh;
    int e = blockIdx.x * blockDim.x + threadIdx.x;   // 0 .. 512*512-1
    int n = e >> 9;
    int k = e & 511;
    g_WT[blockIdx.y][e] = __float2half_rn(W[k * 512 + n]);
}

// ---------------------------------------------------------------------------
// Kernel 3: fp16 GEMM via mma.sync.m16n8k16 (single term).
// CTA tile 128x256, BK=32, 256 threads (8 warps: 2M x 4N, warp tile 64x64).
// 4-stage cp.async pipeline, one __syncthreads per iteration, NIT=16.
// SMEM rows padded to 80B -> conflict-free cp.async stores + ldmatrix.
// grid = (6, 256): x = mat*2 + ntile, y = mtile.
// ---------------------------------------------------------------------------
#define A_STAGE   (128 * 80)                 // 10240 B
#define B_STAGE   (256 * 80)                 // 20480 B
#define STAGE_B   (A_STAGE + B_STAGE)        // 30720 B
#define GEMM_SMEM (4 * STAGE_B)              // 122880 B

__global__ __launch_bounds__(256, 1)
void gemm_kernel() {
    extern __shared__ __align__(128) char dsmem[];
    const uint32_t sbase = smem_u32(dsmem);

    const int tid  = threadIdx.x;
    const int lane = tid & 31;
    const int wid  = tid >> 5;
    const int wm   = (wid & 1) * 64;    // warp M offset in tile
    const int wn   = (wid >> 1) * 64;   // warp N offset in tile

    const int mat   = blockIdx.x >> 1;
    const int nBase = (blockIdx.x & 1) * 256;
    const int mBase = blockIdx.y * 128;

    const __half* Ap = g_A + (size_t)mBase * D_;
    const __half* Wp = g_WT[mat] + (size_t)nBase * D_;
    float* C = g_proj[mat];

    // loader mapping: rows of 32 halfs = 64B = 4 x 16B chunks
    const int lrow = tid >> 2;       // base row (0..63), stepped by +64
    const int lkc  = tid & 3;        // 16B chunk within row

    // ldmatrix per-lane offsets (row stride 80B; two 8x8 k-halves 16B apart)
    const int a_off = (wm + (lane & 15)) * 80 + (lane >> 4) * 16;
    const int b_off = (wn + (lane & 7) + ((lane >> 4) & 1) * 8) * 80
                    + ((lane >> 3) & 1) * 16;

    float acc[4][8][4];
    #pragma unroll
    for (int i = 0; i < 4; ++i)
        #pragma unroll
        for (int j = 0; j < 8; ++j)
            #pragma unroll
            for (int e = 0; e < 4; ++e) acc[i][j][e] = 0.0f;

    auto load_tile = [&](int j) {                // j = k-tile index 0..15
        const int kk = j * 32;
        const uint32_t sa = sbase + (j & 3) * STAGE_B;
        #pragma unroll
        for (int i = 0; i < 2; ++i) {            // A: 2 chunks per thread
            int row = lrow + i * 64;
            cp16(sa + row * 80 + lkc * 16,
                 Ap + (size_t)row * D_ + kk + lkc * 8);
        }
        #pragma unroll
        for (int i = 0; i < 4; ++i) {            // B: 4 chunks per thread
            int row = lrow + i * 64;
            cp16(sa + A_STAGE + row * 80 + lkc * 16,
                 Wp + (size_t)row * D_ + kk + lkc * 8);
        }
    };

    constexpr int NIT = 16;   // 512 / BK
    load_tile(0);
    CP_COMMIT();
    load_tile(1);
    CP_COMMIT();

    for (int it = 0; it < NIT; ++it) {
        // prefetch 2 ahead into buffer (it+2)&3 == (it-2)&3 — its last
        // compute finished before the sync of iteration it-1: hazard-free.
        if (it + 2 < NIT) load_tile(it + 2);
        CP_COMMIT();               // empty commits at tail keep wait math uniform
        CP_WAIT(2);                // buffer (it)&3 is resident
        __syncthreads();

        const uint32_t sa = sbase + (it & 3) * STAGE_B;
        const uint32_t aB = sa + a_off;
        const uint32_t bB = sa + A_STAGE + b_off;

        #pragma unroll
        for (int ks = 0; ks < 2; ++ks) {          // two k16 steps in BK=32
            uint32_t af[4][4], bq[4][4];
            #pragma unroll
            for (int mt = 0; mt < 4; ++mt)
                ldmatrix_x4(af[mt][0], af[mt][1], af[mt][2], af[mt][3],
                            aB + mt * 16 * 80 + ks * 32);
            #pragma unroll
            for (int np = 0; np < 4; ++np)        // each x4 = two n8 b-frags
                ldmatrix_x4(bq[np][0], bq[np][1], bq[np][2], bq[np][3],
                            bB + np * 16 * 80 + ks * 32);
            #pragma unroll
            for (int mt = 0; mt < 4; ++mt)
                #pragma unroll
                for (int nt = 0; nt < 8; ++nt)
                    mma16816(acc[mt][nt], af[mt], &bq[nt >> 1][(nt & 1) * 2]);
        }
    }

    // epilogue
    const int row0 = mBase + wm + (lane >> 2);
    const int col0 = nBase + wn + (lane & 3) * 2;
    #pragma unroll
    for (int mt = 0; mt < 4; ++mt) {
        #pragma unroll
        for (int nt = 0; nt < 8; ++nt) {
            float* p = C + (size_t)(row0 + mt * 16) * H_ + col0 + nt * 8;
            *reinterpret_cast<float2*>(p) =
                make_float2(acc[mt][nt][0], acc[mt][nt][1]);
            *reinterpret_cast<float2*>(p + 8 * H_) =
                make_float2(acc[mt][nt][2], acc[mt][nt][3]);
        }
    }
}

// ---------------------------------------------------------------------------
// Kernel 4: diagonal recurrence scan. TWO h-lanes per thread (float2):
// halves LDG/STG instruction count at equal bytes-in-flight (the binding
// constraint per R3/R5/R6 evidence) and gives ILP=2 on the MUFU chains.
// Depth-16 float2 prefetch ring. 16384 threads, 64/block -> 256 blocks.
// ---------------------------------------------------------------------------
__global__ __launch_bounds__(64)
void scan_kernel(const float* __restrict__ h0,
                 const float* __restrict__ mz, const float* __restrict__ mr,
                 const float* __restrict__ bz, const float* __restrict__ br,
                 float* __restrict__ out)
{
    const int gid = blockIdx.x * 64 + threadIdx.x;   // pair index 0..16383
    const int b = gid >> 8;          // 256 pairs per batch
    const int h = (gid & 255) * 2;   // even h

    float2 hv  = *reinterpret_cast<const float2*>(h0 + (size_t)b * H_ + h);
    const float2 mzv = *reinterpret_cast<const float2*>(mz + h);
    const float2 mrv = *reinterpret_cast<const float2*>(mr + h);
    const float2 bzv = *reinterpret_cast<const float2*>(bz + h);
    const float2 brv = *reinterpret_cast<const float2*>(br + h);

    const size_t base = (size_t)b * T_ * H_ + h;
    const float* xz = g_proj[0] + base;
    const float* xr = g_proj[1] + base;
    const float* xh = g_proj[2] + base;
    float* o = out + base;

    float2 vz[16], vr[16], vh[16];
    #pragma unroll
    for (int i = 0; i < 16; ++i) {
        size_t off = (size_t)i * H_;
        vz[i] = __ldcs(reinterpret_cast<const float2*>(xz + off));
        vr[i] = __ldcs(reinterpret_cast<const float2*>(xr + off));
        vh[i] = __ldcs(reinterpret_cast<const float2*>(xh + off));
    }

    for (int t0 = 0; t0 < T_; t0 += 16) {
        #pragma unroll
        for (int i = 0; i < 16; ++i) {
            const float2 az = make_float2(vz[i].x + bzv.x, vz[i].y + bzv.y);
            const float2 ar = make_float2(vr[i].x + brv.x, vr[i].y + brv.y);
            const float2 ah = vh[i];

            // prefetch t0+i+16 (lands in the padded tail on the last block)
            const size_t poff = (size_t)(t0 + i + 16) * H_;
            vz[i] = __ldcs(reinterpret_cast<const float2*>(xz + poff));
            vr[i] = __ldcs(reinterpret_cast<const float2*>(xr + poff));
            vh[i] = __ldcs(reinterpret_cast<const float2*>(xh + poff));

            // lane 0
            const float r0  = tanh_fast(fmaf(hv.x, mrv.x, ar.x)) + 1.0f;
            const float z0  = __fdividef(1.0f,
                              1.0f + __expf(-fmaf(hv.x, mzv.x, az.x)));
            const float ht0 = tanh_fast(fmaf(r0, hv.x, ah.x));
            // lane 1 (independent chain — ILP)
            const float r1  = tanh_fast(fmaf(hv.y, mrv.y, ar.y)) + 1.0f;
            const float z1  = __fdividef(1.0f,
                              1.0f + __expf(-fmaf(hv.y, mzv.y, az.y)));
            const float ht1 = tanh_fast(fmaf(r1, hv.y, ah.y));

            hv.x = fmaf(z0, hv.x, (1.0f - z0) * ht0);
            hv.y = fmaf(z1, hv.y, (1.0f - z1) * ht1);

            __stcs(reinterpret_cast<float2*>(o + (size_t)(t0 + i) * H_), hv);
        }
    }
}

// ---------------------------------------------------------------------------
extern "C" void kernel_launch(void* const* d_in, const int* in_sizes, int n_in,
                              void* d_out, int out_size)
{
    const float* x  = (const float*)d_in[0];
    const float* h0 = (const float*)d_in[1];
    const float* kz = (const float*)d_in[2];
    const float* kr = (const float*)d_in[3];
    const float* kh = (const float*)d_in[4];
    const float* mz = (const float*)d_in[5];
    const float* mr = (const float*)d_in[6];
    const float* bz = (const float*)d_in[7];
    const float* br = (const float*)d_in[8];
    float* out = (float*)d_out;

    cudaFuncSetAttribute(gemm_kernel,
                         cudaFuncAttributeMaxDynamicSharedMemorySize,
                         GEMM_SMEM);

    // convert x to fp16
    convert_x_kernel<<<(MTOT * D_ / 4) / 256, 256>>>(x);
    // transpose weights to fp16 [N][K]
    convert_w_kernel<<<dim3((H_ * D_) / 256, 3), 256>>>(kz, kr, kh);
    // 3 projections via mma.sync fp16
    gemm_kernel<<<dim3(6, MTOT / 128), 256, GEMM_SMEM>>>();
    // recurrence: 2 lanes per thread
    scan_kernel<<<(B_ * H_ / 2) / 64, 64>>>(h0, mz, mr, bz, br, out);
}

// round 8
// speedup vs baseline: 5.7131x; 1.1334x over previous
#include <cuda_runtime.h>
#include <cuda_fp16.h>
#include <cstdint>
#include <math.h>

#define B_   64
#define T_   512
#define D_   512
#define H_   512
#define MTOT (B_ * T_)          // 32768 GEMM rows

// ---------------------------------------------------------------------------
// Scratch (static __device__ — allocation-guard safe)
// ---------------------------------------------------------------------------
// projections xz, xr, xh (fp32) + 16-step pad for the scan prefetch ring.
__device__ float g_proj[3][(size_t)MTOT * H_ + 16 * H_];
// fp16 x
__device__ __half g_A[(size_t)MTOT * D_];
// fp16 W^T (stored [N][K] K-major)
__device__ __half g_WT[3][H_ * D_];

// ---------------------------------------------------------------------------
// helpers
// ---------------------------------------------------------------------------
__device__ __forceinline__ uint32_t smem_u32(const void* p) {
    return (uint32_t)__cvta_generic_to_shared(p);
}

__device__ __forceinline__ void cp16(uint32_t dst, const void* src) {
    asm volatile("cp.async.cg.shared.global [%0], [%1], 16;"
                 :: "r"(dst), "l"(src) : "memory");
}
#define CP_COMMIT() asm volatile("cp.async.commit_group;" ::: "memory")
#define CP_WAIT(n)  asm volatile("cp.async.wait_group %0;" :: "n"(n) : "memory")

__device__ __forceinline__ void ldmatrix_x4(uint32_t& r0, uint32_t& r1,
                                            uint32_t& r2, uint32_t& r3,
                                            uint32_t addr) {
    asm volatile("ldmatrix.sync.aligned.m8n8.x4.shared.b16 {%0,%1,%2,%3}, [%4];"
                 : "=r"(r0), "=r"(r1), "=r"(r2), "=r"(r3) : "r"(addr));
}
__device__ __forceinline__ void mma16816(float* c, const uint32_t* a,
                                         const uint32_t* b) {
    asm volatile(
        "mma.sync.aligned.m16n8k16.row.col.f32.f16.f16.f32 "
        "{%0,%1,%2,%3}, {%4,%5,%6,%7}, {%8,%9}, {%0,%1,%2,%3};"
        : "+f"(c[0]), "+f"(c[1]), "+f"(c[2]), "+f"(c[3])
        : "r"(a[0]), "r"(a[1]), "r"(a[2]), "r"(a[3]), "r"(b[0]), "r"(b[1]));
}

// HW tanh (MUFU.TANH, sm_75+): ONE MUFU op vs exp+add+rcp chain.
__device__ __forceinline__ float tanh_hw(float x) {
    float y;
    asm("tanh.approx.f32 %0, %1;" : "=f"(y) : "f"(x));
    return y;
}

// ---------------------------------------------------------------------------
// Kernel 1: convert x to fp16
// ---------------------------------------------------------------------------
__global__ __launch_bounds__(256)
void convert_x_kernel(const float* __restrict__ x) {
    size_t i = (size_t)blockIdx.x * blockDim.x + threadIdx.x;   // one float4
    float4 v = reinterpret_cast<const float4*>(x)[i];
    __half2* Hp = reinterpret_cast<__half2*>(g_A);
    Hp[2 * i]     = __halves2half2(__float2half_rn(v.x), __float2half_rn(v.y));
    Hp[2 * i + 1] = __halves2half2(__float2half_rn(v.z), __float2half_rn(v.w));
}

// ---------------------------------------------------------------------------
// Kernel 2: transpose weights to fp16 [N][K]: g_WT[m][n*512+k] = W_m[k*512+n]
// ---------------------------------------------------------------------------
__global__ __launch_bounds__(256)
void convert_w_kernel(const float* __restrict__ kz,
                      const float* __restrict__ kr,
                      const float* __restrict__ kh) {
    const float* W = (blockIdx.y == 0) ? kz : (blockIdx.y == 1) ? kr : kh;
    int e = blockIdx.x * blockDim.x + threadIdx.x;   // 0 .. 512*512-1
    int n = e >> 9;
    int k = e & 511;
    g_WT[blockIdx.y][e] = __float2half_rn(W[k * 512 + n]);
}

// ---------------------------------------------------------------------------
// Kernel 3: fp16 GEMM via mma.sync.m16n8k16 (single term).
// CTA tile 128x256, BK=32, 256 threads (8 warps: 2M x 4N, warp tile 64x64).
// 4-stage cp.async pipeline, one __syncthreads per iteration, NIT=16.
// SMEM rows padded to 80B -> conflict-free cp.async stores + ldmatrix.
// grid = (6, 256): x = mat*2 + ntile, y = mtile.
// ---------------------------------------------------------------------------
#define A_STAGE   (128 * 80)                 // 10240 B
#define B_STAGE   (256 * 80)                 // 20480 B
#define STAGE_B   (A_STAGE + B_STAGE)        // 30720 B
#define GEMM_SMEM (4 * STAGE_B)              // 122880 B

__global__ __launch_bounds__(256, 1)
void gemm_kernel() {
    extern __shared__ __align__(128) char dsmem[];
    const uint32_t sbase = smem_u32(dsmem);

    const int tid  = threadIdx.x;
    const int lane = tid & 31;
    const int wid  = tid >> 5;
    const int wm   = (wid & 1) * 64;    // warp M offset in tile
    const int wn   = (wid >> 1) * 64;   // warp N offset in tile

    const int mat   = blockIdx.x >> 1;
    const int nBase = (blockIdx.x & 1) * 256;
    const int mBase = blockIdx.y * 128;

    const __half* Ap = g_A + (size_t)mBase * D_;
    const __half* Wp = g_WT[mat] + (size_t)nBase * D_;
    float* C = g_proj[mat];

    // loader mapping: rows of 32 halfs = 64B = 4 x 16B chunks
    const int lrow = tid >> 2;       // base row (0..63), stepped by +64
    const int lkc  = tid & 3;        // 16B chunk within row

    // ldmatrix per-lane offsets (row stride 80B; two 8x8 k-halves 16B apart)
    const int a_off = (wm + (lane & 15)) * 80 + (lane >> 4) * 16;
    const int b_off = (wn + (lane & 7) + ((lane >> 4) & 1) * 8) * 80
                    + ((lane >> 3) & 1) * 16;

    float acc[4][8][4];
    #pragma unroll
    for (int i = 0; i < 4; ++i)
        #pragma unroll
        for (int j = 0; j < 8; ++j)
            #pragma unroll
            for (int e = 0; e < 4; ++e) acc[i][j][e] = 0.0f;

    auto load_tile = [&](int j) {                // j = k-tile index 0..15
        const int kk = j * 32;
        const uint32_t sa = sbase + (j & 3) * STAGE_B;
        #pragma unroll
        for (int i = 0; i < 2; ++i) {            // A: 2 chunks per thread
            int row = lrow + i * 64;
            cp16(sa + row * 80 + lkc * 16,
                 Ap + (size_t)row * D_ + kk + lkc * 8);
        }
        #pragma unroll
        for (int i = 0; i < 4; ++i) {            // B: 4 chunks per thread
            int row = lrow + i * 64;
            cp16(sa + A_STAGE + row * 80 + lkc * 16,
                 Wp + (size_t)row * D_ + kk + lkc * 8);
        }
    };

    constexpr int NIT = 16;   // 512 / BK
    load_tile(0);
    CP_COMMIT();
    load_tile(1);
    CP_COMMIT();

    for (int it = 0; it < NIT; ++it) {
        // prefetch 2 ahead into buffer (it+2)&3 == (it-2)&3 — its last
        // compute finished before the sync of iteration it-1: hazard-free.
        if (it + 2 < NIT) load_tile(it + 2);
        CP_COMMIT();               // empty commits at tail keep wait math uniform
        CP_WAIT(2);                // buffer (it)&3 is resident
        __syncthreads();

        const uint32_t sa = sbase + (it & 3) * STAGE_B;
        const uint32_t aB = sa + a_off;
        const uint32_t bB = sa + A_STAGE + b_off;

        #pragma unroll
        for (int ks = 0; ks < 2; ++ks) {          // two k16 steps in BK=32
            uint32_t af[4][4], bq[4][4];
            #pragma unroll
            for (int mt = 0; mt < 4; ++mt)
                ldmatrix_x4(af[mt][0], af[mt][1], af[mt][2], af[mt][3],
                            aB + mt * 16 * 80 + ks * 32);
            #pragma unroll
            for (int np = 0; np < 4; ++np)        // each x4 = two n8 b-frags
                ldmatrix_x4(bq[np][0], bq[np][1], bq[np][2], bq[np][3],
                            bB + np * 16 * 80 + ks * 32);
            #pragma unroll
            for (int mt = 0; mt < 4; ++mt)
                #pragma unroll
                for (int nt = 0; nt < 8; ++nt)
                    mma16816(acc[mt][nt], af[mt], &bq[nt >> 1][(nt & 1) * 2]);
        }
    }

    // epilogue
    const int row0 = mBase + wm + (lane >> 2);
    const int col0 = nBase + wn + (lane & 3) * 2;
    #pragma unroll
    for (int mt = 0; mt < 4; ++mt) {
        #pragma unroll
        for (int nt = 0; nt < 8; ++nt) {
            float* p = C + (size_t)(row0 + mt * 16) * H_ + col0 + nt * 8;
            *reinterpret_cast<float2*>(p) =
                make_float2(acc[mt][nt][0], acc[mt][nt][1]);
            *reinterpret_cast<float2*>(p + 8 * H_) =
                make_float2(acc[mt][nt][2], acc[mt][nt][3]);
        }
    }
}

// ---------------------------------------------------------------------------
// Kernel 4: diagonal recurrence scan. One lane/thread (R6 config — best
// measured). Depth-16 prefetch ring. All activations on MUFU.TANH:
//   tanh -> tanh_hw;  sigmoid(a) = 0.5 + 0.5*tanh_hw(0.5*a)
// MUFU ops/step: 6 -> 3, dependent chain ~110 -> ~50 cyc (MUFU-bound fix).
// ---------------------------------------------------------------------------
__global__ __launch_bounds__(128)
void scan_kernel(const float* __restrict__ h0,
                 const float* __restrict__ mz, const float* __restrict__ mr,
                 const float* __restrict__ bz, const float* __restrict__ br,
                 float* __restrict__ out)
{
    const int gid = blockIdx.x * 128 + threadIdx.x;   // 0 .. B*H-1
    const int b = gid >> 9;
    const int h = gid & 511;

    float hv = h0[gid];
    const float mzv = mz[h];
    const float mrv = mr[h];
    const float bzv = bz[h];
    const float brv = br[h];

    const size_t base = (size_t)b * T_ * H_ + h;
    const float* xz = g_proj[0] + base;
    const float* xr = g_proj[1] + base;
    const float* xh = g_proj[2] + base;
    float* o = out + base;

    float vz[16], vr[16], vh[16];
    #pragma unroll
    for (int i = 0; i < 16; ++i) {
        size_t off = (size_t)i * H_;
        vz[i] = __ldcs(xz + off);
        vr[i] = __ldcs(xr + off);
        vh[i] = __ldcs(xh + off);
    }

    for (int t0 = 0; t0 < T_; t0 += 16) {
        #pragma unroll
        for (int i = 0; i < 16; ++i) {
            const float az = vz[i] + bzv;
            const float ar = vr[i] + brv;
            const float ah = vh[i];

            // prefetch t0+i+16 (lands in the padded tail on the last block)
            const size_t poff = (size_t)(t0 + i + 16) * H_;
            vz[i] = __ldcs(xz + poff);
            vr[i] = __ldcs(xr + poff);
            vh[i] = __ldcs(xh + poff);

            const float r  = tanh_hw(fmaf(hv, mrv, ar)) + 1.0f;
            const float z  = fmaf(0.5f,
                                  tanh_hw(0.5f * fmaf(hv, mzv, az)), 0.5f);
            const float ht = tanh_hw(fmaf(r, hv, ah));
            hv = fmaf(z, hv, (1.0f - z) * ht);

            __stcs(o + (size_t)(t0 + i) * H_, hv);
        }
    }
}

// ---------------------------------------------------------------------------
extern "C" void kernel_launch(void* const* d_in, const int* in_sizes, int n_in,
                              void* d_out, int out_size)
{
    const float* x  = (const float*)d_in[0];
    const float* h0 = (const float*)d_in[1];
    const float* kz = (const float*)d_in[2];
    const float* kr = (const float*)d_in[3];
    const float* kh = (const float*)d_in[4];
    const float* mz = (const float*)d_in[5];
    const float* mr = (const float*)d_in[6];
    const float* bz = (const float*)d_in[7];
    const float* br = (const float*)d_in[8];
    float* out = (float*)d_out;

    cudaFuncSetAttribute(gemm_kernel,
                         cudaFuncAttributeMaxDynamicSharedMemorySize,
                         GEMM_SMEM);

    // convert x to fp16
    convert_x_kernel<<<(MTOT * D_ / 4) / 256, 256>>>(x);
    // transpose weights to fp16 [N][K]
    convert_w_kernel<<<dim3((H_ * D_) / 256, 3), 256>>>(kz, kr, kh);
    // 3 projections via mma.sync fp16
    gemm_kernel<<<dim3(6, MTOT / 128), 256, GEMM_SMEM>>>();
    // recurrence
    scan_kernel<<<(B_ * H_) / 128, 128>>>(h0, mz, mr, bz, br, out);
}

// round 9
// speedup vs baseline: 5.9761x; 1.0460x over previous
#include <cuda_runtime.h>
#include <cuda_fp16.h>
#include <cstdint>
#include <math.h>

#define B_   64
#define T_   512
#define D_   512
#define H_   512
#define MTOT (B_ * T_)          // 32768 GEMM rows

// ---------------------------------------------------------------------------
// Scratch (static __device__ — allocation-guard safe)
// ---------------------------------------------------------------------------
// projections xz, xr, xh in fp16 (halves epilogue-write + scan-read bytes)
// + 32-step pad for the scan prefetch ring.
__device__ __half g_proj[3][(size_t)MTOT * H_ + 32 * H_];
// fp16 x
__device__ __half g_A[(size_t)MTOT * D_];
// fp16 W^T (stored [N][K] K-major)
__device__ __half g_WT[3][H_ * D_];

// ---------------------------------------------------------------------------
// helpers
// ---------------------------------------------------------------------------
__device__ __forceinline__ uint32_t smem_u32(const void* p) {
    return (uint32_t)__cvta_generic_to_shared(p);
}

__device__ __forceinline__ void cp16(uint32_t dst, const void* src) {
    asm volatile("cp.async.cg.shared.global [%0], [%1], 16;"
                 :: "r"(dst), "l"(src) : "memory");
}
#define CP_COMMIT() asm volatile("cp.async.commit_group;" ::: "memory")
#define CP_WAIT(n)  asm volatile("cp.async.wait_group %0;" :: "n"(n) : "memory")

__device__ __forceinline__ void ldmatrix_x4(uint32_t& r0, uint32_t& r1,
                                            uint32_t& r2, uint32_t& r3,
                                            uint32_t addr) {
    asm volatile("ldmatrix.sync.aligned.m8n8.x4.shared.b16 {%0,%1,%2,%3}, [%4];"
                 : "=r"(r0), "=r"(r1), "=r"(r2), "=r"(r3) : "r"(addr));
}
__device__ __forceinline__ void mma16816(float* c, const uint32_t* a,
                                         const uint32_t* b) {
    asm volatile(
        "mma.sync.aligned.m16n8k16.row.col.f32.f16.f16.f32 "
        "{%0,%1,%2,%3}, {%4,%5,%6,%7}, {%8,%9}, {%0,%1,%2,%3};"
        : "+f"(c[0]), "+f"(c[1]), "+f"(c[2]), "+f"(c[3])
        : "r"(a[0]), "r"(a[1]), "r"(a[2]), "r"(a[3]), "r"(b[0]), "r"(b[1]));
}

// HW tanh (MUFU.TANH, sm_75+): ONE MUFU op vs exp+add+rcp chain.
__device__ __forceinline__ float tanh_hw(float x) {
    float y;
    asm("tanh.approx.f32 %0, %1;" : "=f"(y) : "f"(x));
    return y;
}

// streaming 2-byte load -> fp32
__device__ __forceinline__ float ldcs_h2f(const __half* p) {
    unsigned short u = __ldcs(reinterpret_cast<const unsigned short*>(p));
    return __half2float(__ushort_as_half(u));
}

// ---------------------------------------------------------------------------
// Kernel 1: convert x to fp16
// ---------------------------------------------------------------------------
__global__ __launch_bounds__(256)
void convert_x_kernel(const float* __restrict__ x) {
    size_t i = (size_t)blockIdx.x * blockDim.x + threadIdx.x;   // one float4
    float4 v = reinterpret_cast<const float4*>(x)[i];
    __half2* Hp = reinterpret_cast<__half2*>(g_A);
    Hp[2 * i]     = __halves2half2(__float2half_rn(v.x), __float2half_rn(v.y));
    Hp[2 * i + 1] = __halves2half2(__float2half_rn(v.z), __float2half_rn(v.w));
}

// ---------------------------------------------------------------------------
// Kernel 2: transpose weights to fp16 [N][K]: g_WT[m][n*512+k] = W_m[k*512+n]
// ---------------------------------------------------------------------------
__global__ __launch_bounds__(256)
void convert_w_kernel(const float* __restrict__ kz,
                      const float* __restrict__ kr,
                      const float* __restrict__ kh) {
    const float* W = (blockIdx.y == 0) ? kz : (blockIdx.y == 1) ? kr : kh;
    int e = blockIdx.x * blockDim.x + threadIdx.x;   // 0 .. 512*512-1
    int n = e >> 9;
    int k = e & 511;
    g_WT[blockIdx.y][e] = __float2half_rn(W[k * 512 + n]);
}

// ---------------------------------------------------------------------------
// Kernel 3: fp16 GEMM via mma.sync.m16n8k16.
// CTA tile 128x256, BK=32, 256 threads (8 warps: 2M x 4N, warp tile 64x64).
// 4-stage cp.async pipeline, one __syncthreads per iteration, NIT=16.
// SMEM rows padded to 80B -> conflict-free cp.async stores + ldmatrix.
// Epilogue packs fp32 accumulators to fp16 (half the write bytes).
// grid = (6, 256): x = mat*2 + ntile, y = mtile.
// ---------------------------------------------------------------------------
#define A_STAGE   (128 * 80)                 // 10240 B
#define B_STAGE   (256 * 80)                 // 20480 B
#define STAGE_B   (A_STAGE + B_STAGE)        // 30720 B
#define GEMM_SMEM (4 * STAGE_B)              // 122880 B

__global__ __launch_bounds__(256, 1)
void gemm_kernel() {
    extern __shared__ __align__(128) char dsmem[];
    const uint32_t sbase = smem_u32(dsmem);

    const int tid  = threadIdx.x;
    const int lane = tid & 31;
    const int wid  = tid >> 5;
    const int wm   = (wid & 1) * 64;    // warp M offset in tile
    const int wn   = (wid >> 1) * 64;   // warp N offset in tile

    const int mat   = blockIdx.x >> 1;
    const int nBase = (blockIdx.x & 1) * 256;
    const int mBase = blockIdx.y * 128;

    const __half* Ap = g_A + (size_t)mBase * D_;
    const __half* Wp = g_WT[mat] + (size_t)nBase * D_;
    __half* C = g_proj[mat];

    // loader mapping: rows of 32 halfs = 64B = 4 x 16B chunks
    const int lrow = tid >> 2;       // base row (0..63), stepped by +64
    const int lkc  = tid & 3;        // 16B chunk within row

    // ldmatrix per-lane offsets (row stride 80B; two 8x8 k-halves 16B apart)
    const int a_off = (wm + (lane & 15)) * 80 + (lane >> 4) * 16;
    const int b_off = (wn + (lane & 7) + ((lane >> 4) & 1) * 8) * 80
                    + ((lane >> 3) & 1) * 16;

    float acc[4][8][4];
    #pragma unroll
    for (int i = 0; i < 4; ++i)
        #pragma unroll
        for (int j = 0; j < 8; ++j)
            #pragma unroll
            for (int e = 0; e < 4; ++e) acc[i][j][e] = 0.0f;

    auto load_tile = [&](int j) {                // j = k-tile index 0..15
        const int kk = j * 32;
        const uint32_t sa = sbase + (j & 3) * STAGE_B;
        #pragma unroll
        for (int i = 0; i < 2; ++i) {            // A: 2 chunks per thread
            int row = lrow + i * 64;
            cp16(sa + row * 80 + lkc * 16,
                 Ap + (size_t)row * D_ + kk + lkc * 8);
        }
        #pragma unroll
        for (int i = 0; i < 4; ++i) {            // B: 4 chunks per thread
            int row = lrow + i * 64;
            cp16(sa + A_STAGE + row * 80 + lkc * 16,
                 Wp + (size_t)row * D_ + kk + lkc * 8);
        }
    };

    constexpr int NIT = 16;   // 512 / BK
    load_tile(0);
    CP_COMMIT();
    load_tile(1);
    CP_COMMIT();

    for (int it = 0; it < NIT; ++it) {
        // prefetch 2 ahead into buffer (it+2)&3 == (it-2)&3 — its last
        // compute finished before the sync of iteration it-1: hazard-free.
        if (it + 2 < NIT) load_tile(it + 2);
        CP_COMMIT();               // empty commits at tail keep wait math uniform
        CP_WAIT(2);                // buffer (it)&3 is resident
        __syncthreads();

        const uint32_t sa = sbase + (it & 3) * STAGE_B;
        const uint32_t aB = sa + a_off;
        const uint32_t bB = sa + A_STAGE + b_off;

        #pragma unroll
        for (int ks = 0; ks < 2; ++ks) {          // two k16 steps in BK=32
            uint32_t af[4][4], bq[4][4];
            #pragma unroll
            for (int mt = 0; mt < 4; ++mt)
                ldmatrix_x4(af[mt][0], af[mt][1], af[mt][2], af[mt][3],
                            aB + mt * 16 * 80 + ks * 32);
            #pragma unroll
            for (int np = 0; np < 4; ++np)        // each x4 = two n8 b-frags
                ldmatrix_x4(bq[np][0], bq[np][1], bq[np][2], bq[np][3],
                            bB + np * 16 * 80 + ks * 32);
            #pragma unroll
            for (int mt = 0; mt < 4; ++mt)
                #pragma unroll
                for (int nt = 0; nt < 8; ++nt)
                    mma16816(acc[mt][nt], af[mt], &bq[nt >> 1][(nt & 1) * 2]);
        }
    }

    // epilogue: pack adjacent col pairs to half2 (4B stores)
    const int row0 = mBase + wm + (lane >> 2);
    const int col0 = nBase + wn + (lane & 3) * 2;
    #pragma unroll
    for (int mt = 0; mt < 4; ++mt) {
        #pragma unroll
        for (int nt = 0; nt < 8; ++nt) {
            __half* p = C + (size_t)(row0 + mt * 16) * H_ + col0 + nt * 8;
            *reinterpret_cast<__half2*>(p) =
                __floats2half2_rn(acc[mt][nt][0], acc[mt][nt][1]);
            *reinterpret_cast<__half2*>(p + 8 * H_) =
                __floats2half2_rn(acc[mt][nt][2], acc[mt][nt][3]);
        }
    }
}

// ---------------------------------------------------------------------------
// Kernel 4: diagonal recurrence scan. One lane/thread, depth-32 prefetch
// ring over fp16 projections (32x3x2B x 32768 thr = 6.3 MB in flight,
// matching the BW*latency product). MUFU.TANH activations.
// ---------------------------------------------------------------------------
__global__ __launch_bounds__(128)
void scan_kernel(const float* __restrict__ h0,
                 const float* __restrict__ mz, const float* __restrict__ mr,
                 const float* __restrict__ bz, const float* __restrict__ br,
                 float* __restrict__ out)
{
    const int gid = blockIdx.x * 128 + threadIdx.x;   // 0 .. B*H-1
    const int b = gid >> 9;
    const int h = gid & 511;

    float hv = h0[gid];
    const float mzv = mz[h];
    const float mrv = mr[h];
    const float bzv = bz[h];
    const float brv = br[h];

    const size_t base = (size_t)b * T_ * H_ + h;
    const __half* xz = g_proj[0] + base;
    const __half* xr = g_proj[1] + base;
    const __half* xh = g_proj[2] + base;
    float* o = out + base;

    float vz[32], vr[32], vh[32];
    #pragma unroll
    for (int i = 0; i < 32; ++i) {
        size_t off = (size_t)i * H_;
        vz[i] = ldcs_h2f(xz + off);
        vr[i] = ldcs_h2f(xr + off);
        vh[i] = ldcs_h2f(xh + off);
    }

    for (int t0 = 0; t0 < T_; t0 += 32) {
        #pragma unroll
        for (int i = 0; i < 32; ++i) {
            const float az = vz[i] + bzv;
            const float ar = vr[i] + brv;
            const float ah = vh[i];

            // prefetch t0+i+32 (lands in the padded tail on the last block)
            const size_t poff = (size_t)(t0 + i + 32) * H_;
            vz[i] = ldcs_h2f(xz + poff);
            vr[i] = ldcs_h2f(xr + poff);
            vh[i] = ldcs_h2f(xh + poff);

            const float r  = tanh_hw(fmaf(hv, mrv, ar)) + 1.0f;
            const float z  = fmaf(0.5f,
                                  tanh_hw(0.5f * fmaf(hv, mzv, az)), 0.5f);
            const float ht = tanh_hw(fmaf(r, hv, ah));
            hv = fmaf(z, hv, (1.0f - z) * ht);

            __stcs(o + (size_t)(t0 + i) * H_, hv);
        }
    }
}

// ---------------------------------------------------------------------------
extern "C" void kernel_launch(void* const* d_in, const int* in_sizes, int n_in,
                              void* d_out, int out_size)
{
    const float* x  = (const float*)d_in[0];
    const float* h0 = (const float*)d_in[1];
    const float* kz = (const float*)d_in[2];
    const float* kr = (const float*)d_in[3];
    const float* kh = (const float*)d_in[4];
    const float* mz = (const float*)d_in[5];
    const float* mr = (const float*)d_in[6];
    const float* bz = (const float*)d_in[7];
    const float* br = (const float*)d_in[8];
    float* out = (float*)d_out;

    cudaFuncSetAttribute(gemm_kernel,
                         cudaFuncAttributeMaxDynamicSharedMemorySize,
                         GEMM_SMEM);

    // convert x to fp16
    convert_x_kernel<<<(MTOT * D_ / 4) / 256, 256>>>(x);
    // transpose weights to fp16 [N][K]
    convert_w_kernel<<<dim3((H_ * D_) / 256, 3), 256>>>(kz, kr, kh);
    // 3 projections via mma.sync fp16, fp16 output
    gemm_kernel<<<dim3(6, MTOT / 128), 256, GEMM_SMEM>>>();
    // recurrence
    scan_kernel<<<(B_ * H_) / 128, 128>>>(h0, mz, mr, bz, br, out);
}